// round 10
// baseline (speedup 1.0000x reference)
#include <cuda_runtime.h>
#include <cuda_fp16.h>
#include <cstdint>

// Problem constants (fixed by setup_inputs)
#define NBL    16      // b*l
#define NHEADS 16
#define SEQ    512
#define DH     64
#define EMB    1024
#define NCOLS  3072    // 3*EMB

// fp16 scratch: head-major Q/K/V [bl][h][n][d]; converted inputs
__device__ __half g_Q[(size_t)NBL * NHEADS * SEQ * DH];
__device__ __half g_K[(size_t)NBL * NHEADS * SEQ * DH];
__device__ __half g_V[(size_t)NBL * NHEADS * SEQ * DH];
__device__ __half g_X[(size_t)NBL * SEQ * EMB];    // x, fp16
__device__ __half g_WT[(size_t)NCOLS * EMB];       // w^T, fp16

// ============================================================================
// Helpers
// ============================================================================
__device__ __forceinline__ uint32_t smem_u32(const void* p) {
    uint32_t a;
    asm("{ .reg .u64 t; cvta.to.shared.u64 t, %1; cvt.u32.u64 %0, t; }" : "=r"(a) : "l"(p));
    return a;
}

__device__ __forceinline__ void ldsm4(unsigned& r0, unsigned& r1, unsigned& r2,
                                      unsigned& r3, uint32_t addr) {
    asm volatile("ldmatrix.sync.aligned.m8n8.x4.shared.b16 {%0,%1,%2,%3}, [%4];"
                 : "=r"(r0), "=r"(r1), "=r"(r2), "=r"(r3) : "r"(addr));
}
__device__ __forceinline__ void ldsm4t(unsigned& r0, unsigned& r1, unsigned& r2,
                                       unsigned& r3, uint32_t addr) {
    asm volatile("ldmatrix.sync.aligned.m8n8.x4.trans.shared.b16 {%0,%1,%2,%3}, [%4];"
                 : "=r"(r0), "=r"(r1), "=r"(r2), "=r"(r3) : "r"(addr));
}

// D(16x8) += A(16x16) * B(16x8), fp16 in, fp32 accum
__device__ __forceinline__ void mma_f16(float* c, const unsigned* a, const unsigned* b) {
    asm volatile(
        "mma.sync.aligned.m16n8k16.row.col.f32.f16.f16.f32 "
        "{%0,%1,%2,%3}, {%4,%5,%6,%7}, {%8,%9}, {%0,%1,%2,%3};"
        : "+f"(c[0]), "+f"(c[1]), "+f"(c[2]), "+f"(c[3])
        : "r"(a[0]), "r"(a[1]), "r"(a[2]), "r"(a[3]), "r"(b[0]), "r"(b[1]));
}

__device__ __forceinline__ unsigned packh2(float a, float b) {
    __half2 h = __floats2half2_rn(a, b);
    return *(unsigned*)&h;
}

#define CP_ASYNC16(dst, src) \
    asm volatile("cp.async.cg.shared.global [%0], [%1], 16;" :: "r"(dst), "l"(src))
#define CP_COMMIT() asm volatile("cp.async.commit_group;" ::: "memory")
#define CP_WAIT2()  asm volatile("cp.async.wait_group 2;" ::: "memory")
#define CP_WAIT1()  asm volatile("cp.async.wait_group 1;" ::: "memory")
#define CP_WAIT0()  asm volatile("cp.async.wait_group 0;" ::: "memory")

// ============================================================================
// Pre-pass: x -> fp16 (g_X); w -> transposed fp16 (g_WT)
// ============================================================================
__global__ __launch_bounds__(256) void cvt_x_kernel(const float* __restrict__ x) {
    const int i = blockIdx.x * 256 + threadIdx.x;        // float4 index
    float4 v = ((const float4*)x)[i];
    uint2 o;
    o.x = packh2(v.x, v.y);
    o.y = packh2(v.z, v.w);
    ((uint2*)g_X)[i] = o;
}

__global__ __launch_bounds__(256) void cvt_wT_kernel(const float* __restrict__ w) {
    __shared__ float tile[32][33];
    const int tx = threadIdx.x & 31;
    const int ty = threadIdx.x >> 5;                     // 0..7
    const int n0 = blockIdx.x * 32;
    const int k0 = blockIdx.y * 32;
#pragma unroll
    for (int r = ty; r < 32; r += 8)
        tile[r][tx] = w[(size_t)(k0 + r) * NCOLS + n0 + tx];
    __syncthreads();
#pragma unroll
    for (int r = ty; r < 32; r += 8)
        g_WT[(size_t)(n0 + r) * EMB + k0 + tx] = __float2half_rn(tile[tx][r]);
}

// ============================================================================
// QKV GEMM: M=8192, N=3072, K=1024, fp16 m16n8k16 + ldmatrix.
// CTA tile 128x64, BK=64 (16 chunks), 2-stage cp.async, one barrier/chunk.
// 4 warps, warp tile 64x32. ybase selects the bl half (units of 128 rows).
// ============================================================================
#define ESTR 72                          // 64 + 8 halves pad -> conflict-free LDSM
#define QKV_A_BYTES (128 * ESTR * 2)     // 18432
#define QKV_B_BYTES (64 * ESTR * 2)      // 9216
#define QKV_STAGE   (QKV_A_BYTES + QKV_B_BYTES)  // 27648
#define QKV_SMEM    (2 * QKV_STAGE)      // 55296 bytes

__global__ __launch_bounds__(128, 3) void qkv_kernel(const float* __restrict__ bias,
                                                     int ybase)
{
    extern __shared__ __half qsm[];
    const uint32_t sBase = smem_u32(qsm);

    const int tid  = threadIdx.x;
    const int lane = tid & 31;
    const int warp = tid >> 5;        // 0..3
    const int wm = warp & 1;          // 2 warps along M (64 rows each)
    const int wn = warp >> 1;         // 2 warps along N (32 cols each)
    const int r4 = lane >> 2;
    const int c4 = lane & 3;
    const int lrow = lane & 15;
    const int lch  = (lane >> 4) * 8;

    const int m0 = (ybase + blockIdx.y) * 128;
    const int c0 = blockIdx.x * 64;

    float acc[4][4][4];
#pragma unroll
    for (int i = 0; i < 4; i++)
#pragma unroll
        for (int j = 0; j < 4; j++)
#pragma unroll
            for (int k = 0; k < 4; k++) acc[i][j][k] = 0.f;

    // per stage: A 1024 chunks (8/thread), B 512 chunks (4/thread)
#define QKV_LOAD(kc, s) do { \
    const size_t gk = (size_t)(kc) * 64; \
    const uint32_t aB_ = sBase + (uint32_t)(s) * QKV_STAGE; \
    const uint32_t bB_ = aB_ + QKV_A_BYTES; \
    _Pragma("unroll") \
    for (int i = 0; i < 8; i++) { \
        const int fid = i * 128 + tid; \
        const int row = fid >> 3; \
        const int chh = (fid & 7) * 8; \
        CP_ASYNC16(aB_ + (row * ESTR + chh) * 2, \
                   g_X + (size_t)(m0 + row) * EMB + gk + chh); \
    } \
    _Pragma("unroll") \
    for (int i = 0; i < 4; i++) { \
        const int fid = i * 128 + tid; \
        const int row = fid >> 3; \
        const int chh = (fid & 7) * 8; \
        CP_ASYNC16(bB_ + (row * ESTR + chh) * 2, \
                   g_WT + (size_t)(c0 + row) * EMB + gk + chh); \
    } \
    CP_COMMIT(); \
} while (0)

    QKV_LOAD(0, 0);

#pragma unroll 1
    for (int kc = 0; kc < 16; kc++) {
        CP_WAIT0();                       // stage kc landed (only group pending)
        __syncthreads();                  // all warps done computing stage kc-1
        if (kc + 1 < 16) QKV_LOAD(kc + 1, (kc + 1) & 1);

        const uint32_t aB = sBase + (kc & 1) * QKV_STAGE;
        const uint32_t bB = aB + QKV_A_BYTES;

#pragma unroll
        for (int ks = 0; ks < 4; ks++) {
            unsigned a[4][4];
#pragma unroll
            for (int mt = 0; mt < 4; mt++)
                ldsm4(a[mt][0], a[mt][1], a[mt][2], a[mt][3],
                      aB + ((wm * 64 + mt * 16 + lrow) * ESTR + ks * 16 + lch) * 2);
            unsigned b[4][2];
#pragma unroll
            for (int ntp = 0; ntp < 2; ntp++) {
                unsigned t0, t1, t2, t3;
                ldsm4(t0, t1, t2, t3,
                      bB + ((wn * 32 + ntp * 16 + lrow) * ESTR + ks * 16 + lch) * 2);
                b[2 * ntp][0] = t0; b[2 * ntp][1] = t2;
                b[2 * ntp + 1][0] = t1; b[2 * ntp + 1][1] = t3;
            }
#pragma unroll
            for (int mt = 0; mt < 4; mt++)
#pragma unroll
                for (int nt = 0; nt < 4; nt++)
                    mma_f16(acc[mt][nt], a[mt], b[nt]);
        }
    }

    // Epilogue: bias add, fp16, scatter to head-major Q/K/V
#pragma unroll
    for (int mt = 0; mt < 4; mt++) {
        const int mg = m0 + wm * 64 + mt * 16 + r4;
        const int bl = mg >> 9;
        const int n  = mg & 511;
#pragma unroll
        for (int nt = 0; nt < 4; nt++) {
            const int colg = c0 + wn * 32 + nt * 8 + 2 * c4;
            const int which = colg >> 10;
            const int h     = (colg >> 6) & 15;
            const int d     = colg & 63;
            __half* dst = ((which == 0) ? g_Q : (which == 1) ? g_K : g_V)
                        + (size_t)(bl * NHEADS + h) * SEQ * DH + d;
            const float b0 = __ldg(&bias[colg]);
            const float b1 = __ldg(&bias[colg + 1]);
            *(__half2*)(dst + (size_t)n * DH) =
                __floats2half2_rn(acc[mt][nt][0] + b0, acc[mt][nt][1] + b1);
            *(__half2*)(dst + (size_t)(n + 8) * DH) =
                __floats2half2_rn(acc[mt][nt][2] + b0, acc[mt][nt][3] + b1);
        }
    }
}

// ============================================================================
// Fused flash attention: CTA = (head, 64 Q rows), 4 warps x 16 rows.
// 3-stage cp.async K/V pipeline, one barrier per KV block. fp16 MMA.
// P fragments built DIRECTLY from S accumulators. gbase selects the bl half.
// ============================================================================
#define PSTR 72
#define KSTR 72
#define KV_BYTES (64 * KSTR * 2)                 // 9216 per matrix per stage
#define ATTN_SMEM (64 * PSTR * 2 + 6 * KV_BYTES) // 64512

__global__ __launch_bounds__(128, 3) void attn_kernel(
    const float* __restrict__ mask, float* __restrict__ out, int gbase)
{
    extern __shared__ __half asm_[];
    const uint32_t pBase  = smem_u32(asm_);
    const uint32_t kvBase = pBase + 64 * PSTR * 2;

    const int tid  = threadIdx.x;
    const int lane = tid & 31;
    const int warp = tid >> 5;         // 0..3
    const int r4 = lane >> 2;
    const int c4 = lane & 3;
    const int lrow = lane & 15;
    const int lch  = (lane >> 4) * 8;

    const int g  = gbase + blockIdx.y; // bl*16 + h
    const int bl = g >> 4;
    const int h  = g & 15;
    const int q0 = blockIdx.x * 64;
    const int qr0 = warp * 16;

    const __half* Qg = g_Q + (size_t)g * SEQ * DH;
    const __half* Kg = g_K + (size_t)g * SEQ * DH;
    const __half* Vg = g_V + (size_t)g * SEQ * DH;
    const float*  Mg = mask + (size_t)bl * SEQ * SEQ + (size_t)q0 * SEQ;

    // ---- Q staging (cp.async, own commit group) ----
#pragma unroll
    for (int i = 0; i < 4; i++) {
        const int fid = i * 128 + tid;          // 512 chunks
        const int row = fid >> 3;
        const int chh = (fid & 7) * 8;
        CP_ASYNC16(pBase + (row * PSTR + chh) * 2,
                   Qg + (size_t)(q0 + row) * DH + chh);
    }
    CP_COMMIT();

#define KV_LOAD(kb, s) do { \
    const uint32_t kA = kvBase + (uint32_t)(s) * 2 * KV_BYTES; \
    const uint32_t vA = kA + KV_BYTES; \
    const int kk0 = (kb) * 64; \
    _Pragma("unroll") \
    for (int i = 0; i < 4; i++) { \
        const int fid = i * 128 + tid; \
        const int row = fid >> 3; \
        const int chh = (fid & 7) * 8; \
        CP_ASYNC16(kA + (row * KSTR + chh) * 2, Kg + (size_t)(kk0 + row) * DH + chh); \
        CP_ASYNC16(vA + (row * KSTR + chh) * 2, Vg + (size_t)(kk0 + row) * DH + chh); \
    } \
    CP_COMMIT(); \
} while (0)

    KV_LOAD(0, 0);
    KV_LOAD(1, 1);

    CP_WAIT2();                        // Q group done
    __syncthreads();

    unsigned qf[4][4];
#pragma unroll
    for (int kt = 0; kt < 4; kt++)
        ldsm4(qf[kt][0], qf[kt][1], qf[kt][2], qf[kt][3],
              pBase + ((qr0 + lrow) * PSTR + kt * 16 + lch) * 2);

    float m_i0 = -1e30f, m_i1 = -1e30f;
    float l_i0 = 0.f,    l_i1 = 0.f;
    float o[8][4];
#pragma unroll
    for (int nt = 0; nt < 8; nt++)
#pragma unroll
        for (int j = 0; j < 4; j++) o[nt][j] = 0.f;

#pragma unroll 1
    for (int kb = 0; kb < 8; kb++) {
        if (kb < 7) CP_WAIT1(); else CP_WAIT0();
        __syncthreads();               // everyone done with stage (kb+2)%3
        if (kb + 2 < 8) KV_LOAD(kb + 2, (kb + 2) % 3);

        const uint32_t kB = kvBase + (kb % 3) * 2 * KV_BYTES;
        const uint32_t vB = kB + KV_BYTES;
        const int k0 = kb * 64;

        // ---- S = Q K^T  (16x64 per warp) ----
        float s[8][4];
#pragma unroll
        for (int nt = 0; nt < 8; nt++)
#pragma unroll
            for (int j = 0; j < 4; j++) s[nt][j] = 0.f;

#pragma unroll
        for (int kt = 0; kt < 4; kt++) {
#pragma unroll
            for (int ntp = 0; ntp < 4; ntp++) {
                unsigned t0, t1, t2, t3;
                ldsm4(t0, t1, t2, t3,
                      kB + ((ntp * 16 + lrow) * KSTR + kt * 16 + lch) * 2);
                unsigned b0[2] = {t0, t2};
                unsigned b1[2] = {t1, t3};
                mma_f16(s[2 * ntp],     qf[kt], b0);
                mma_f16(s[2 * ntp + 1], qf[kt], b1);
            }
        }

        // ---- scale + mask, row max ----
        float mx0 = -1e30f, mx1 = -1e30f;
#pragma unroll
        for (int nt = 0; nt < 8; nt++) {
            const int col = k0 + nt * 8 + c4 * 2;
            const float* mrow = Mg + (size_t)(qr0 + r4) * SEQ + col;
            const float2 mk0 = *(const float2*)mrow;
            const float2 mk1 = *(const float2*)(mrow + 8 * SEQ);
            s[nt][0] = s[nt][0] * 0.125f + mk0.x;
            s[nt][1] = s[nt][1] * 0.125f + mk0.y;
            s[nt][2] = s[nt][2] * 0.125f + mk1.x;
            s[nt][3] = s[nt][3] * 0.125f + mk1.y;
            mx0 = fmaxf(mx0, fmaxf(s[nt][0], s[nt][1]));
            mx1 = fmaxf(mx1, fmaxf(s[nt][2], s[nt][3]));
        }
        mx0 = fmaxf(mx0, __shfl_xor_sync(0xFFFFFFFFu, mx0, 1));
        mx0 = fmaxf(mx0, __shfl_xor_sync(0xFFFFFFFFu, mx0, 2));
        mx1 = fmaxf(mx1, __shfl_xor_sync(0xFFFFFFFFu, mx1, 1));
        mx1 = fmaxf(mx1, __shfl_xor_sync(0xFFFFFFFFu, mx1, 2));

        const float mn0 = fmaxf(m_i0, mx0);
        const float mn1 = fmaxf(m_i1, mx1);
        const float sc0 = __expf(m_i0 - mn0);
        const float sc1 = __expf(m_i1 - mn1);
        m_i0 = mn0; m_i1 = mn1;

        float sum0 = 0.f, sum1 = 0.f;
#pragma unroll
        for (int nt = 0; nt < 8; nt++) {
            s[nt][0] = __expf(s[nt][0] - mn0);
            s[nt][1] = __expf(s[nt][1] - mn0);
            s[nt][2] = __expf(s[nt][2] - mn1);
            s[nt][3] = __expf(s[nt][3] - mn1);
            sum0 += s[nt][0] + s[nt][1];
            sum1 += s[nt][2] + s[nt][3];
        }
        sum0 += __shfl_xor_sync(0xFFFFFFFFu, sum0, 1);
        sum0 += __shfl_xor_sync(0xFFFFFFFFu, sum0, 2);
        sum1 += __shfl_xor_sync(0xFFFFFFFFu, sum1, 1);
        sum1 += __shfl_xor_sync(0xFFFFFFFFu, sum1, 2);
        l_i0 = l_i0 * sc0 + sum0;
        l_i1 = l_i1 * sc1 + sum1;

        // ---- rescale O ----
#pragma unroll
        for (int nt = 0; nt < 8; nt++) {
            o[nt][0] *= sc0; o[nt][1] *= sc0;
            o[nt][2] *= sc1; o[nt][3] *= sc1;
        }

        // ---- O += P V, P fragments straight from S accumulators ----
#pragma unroll
        for (int kt = 0; kt < 4; kt++) {
            unsigned pf[4];
            pf[0] = packh2(s[2 * kt][0],     s[2 * kt][1]);
            pf[1] = packh2(s[2 * kt][2],     s[2 * kt][3]);
            pf[2] = packh2(s[2 * kt + 1][0], s[2 * kt + 1][1]);
            pf[3] = packh2(s[2 * kt + 1][2], s[2 * kt + 1][3]);
#pragma unroll
            for (int dtp = 0; dtp < 4; dtp++) {
                unsigned t0, t1, t2, t3;
                ldsm4t(t0, t1, t2, t3,
                       vB + ((kt * 16 + lrow) * KSTR + dtp * 16 + lch) * 2);
                unsigned b0[2] = {t0, t1};
                unsigned b1[2] = {t2, t3};
                mma_f16(o[2 * dtp],     pf, b0);
                mma_f16(o[2 * dtp + 1], pf, b1);
            }
        }
    }

    // ---- normalize + write out ----
    const float inv0 = 1.f / l_i0;
    const float inv1 = 1.f / l_i1;
    const int grow = q0 + qr0 + r4;
    float* outp = out + (size_t)(bl * SEQ + grow) * EMB + h * DH;
#pragma unroll
    for (int nt = 0; nt < 8; nt++) {
        const int col = nt * 8 + c4 * 2;
        *(float2*)(outp + col) =
            make_float2(o[nt][0] * inv0, o[nt][1] * inv0);
        *(float2*)(outp + (size_t)8 * EMB + col) =
            make_float2(o[nt][2] * inv1, o[nt][3] * inv1);
    }
}

// ============================================================================
// Static stream/event set (created once at process init; no device memory).
// ============================================================================
struct OverlapCtx {
    cudaStream_t s1;
    cudaEvent_t eFork, eWT, eA, eB, eDone;
    OverlapCtx() {
        cudaStreamCreateWithFlags(&s1, cudaStreamNonBlocking);
        cudaEventCreateWithFlags(&eFork, cudaEventDisableTiming);
        cudaEventCreateWithFlags(&eWT,   cudaEventDisableTiming);
        cudaEventCreateWithFlags(&eA,    cudaEventDisableTiming);
        cudaEventCreateWithFlags(&eB,    cudaEventDisableTiming);
        cudaEventCreateWithFlags(&eDone, cudaEventDisableTiming);
    }
};
static OverlapCtx g_ov;

// ============================================================================
// Launch: fork-join two streams so attn(first half) overlaps qkv(second half)
// ============================================================================
extern "C" void kernel_launch(void* const* d_in, const int* in_sizes, int n_in,
                              void* d_out, int out_size)
{
    const float* x = nullptr; const float* mask = nullptr;
    const float* w = nullptr; const float* bias = nullptr;
    for (int i = 0; i < n_in; i++) {
        switch (in_sizes[i]) {
            case 8388608: x    = (const float*)d_in[i]; break;  // 4*4*512*1024
            case 4194304: mask = (const float*)d_in[i]; break;  // 4*4*512*512
            case 3145728: w    = (const float*)d_in[i]; break;  // 1024*3072
            case 3072:    bias = (const float*)d_in[i]; break;
        }
    }
    float* out = (float*)d_out;

    cudaStream_t s0 = 0;               // capture-origin (legacy) stream
    cudaStream_t s1 = g_ov.s1;

    cudaFuncSetAttribute(qkv_kernel,
                         cudaFuncAttributeMaxDynamicSharedMemorySize, QKV_SMEM);
    cudaFuncSetAttribute(attn_kernel,
                         cudaFuncAttributeMaxDynamicSharedMemorySize, ATTN_SMEM);

    // fork s1 from s0
    cudaEventRecord(g_ov.eFork, s0);
    cudaStreamWaitEvent(s1, g_ov.eFork, 0);

    // prepass: cvt_x on s0, cvt_wT on s1 (concurrent)
    cvt_x_kernel<<<8192, 256, 0, s0>>>(x);
    cvt_wT_kernel<<<dim3(96, 32), 256, 0, s1>>>(w);
    cudaEventRecord(g_ov.eWT, s1);
    cudaStreamWaitEvent(s0, g_ov.eWT, 0);          // qkv needs g_WT too

    // qkv halves on s0
    qkv_kernel<<<dim3(48, 32), 128, QKV_SMEM, s0>>>(bias, 0);   // bl 0-7
    cudaEventRecord(g_ov.eA, s0);
    qkv_kernel<<<dim3(48, 32), 128, QKV_SMEM, s0>>>(bias, 32);  // bl 8-15
    cudaEventRecord(g_ov.eB, s0);

    // attn halves on s1: attnA overlaps qkvB
    cudaStreamWaitEvent(s1, g_ov.eA, 0);
    attn_kernel<<<dim3(8, 128), 128, ATTN_SMEM, s1>>>(mask, out, 0);    // bl 0-7
    cudaStreamWaitEvent(s1, g_ov.eB, 0);
    attn_kernel<<<dim3(8, 128), 128, ATTN_SMEM, s1>>>(mask, out, 128);  // bl 8-15

    // join back to s0
    cudaEventRecord(g_ov.eDone, s1);
    cudaStreamWaitEvent(s0, g_ov.eDone, 0);
}

// round 11
// speedup vs baseline: 1.0003x; 1.0003x over previous
#include <cuda_runtime.h>
#include <cuda_fp16.h>
#include <cstdint>

// Problem constants (fixed by setup_inputs)
#define NBL    16      // b*l
#define NHEADS 16
#define SEQ    512
#define DH     64
#define EMB    1024
#define NCOLS  3072    // 3*EMB

// fp16 scratch: head-major Q/K/V [bl][h][n][d]; converted inputs
__device__ __half g_Q[(size_t)NBL * NHEADS * SEQ * DH];
__device__ __half g_K[(size_t)NBL * NHEADS * SEQ * DH];
__device__ __half g_V[(size_t)NBL * NHEADS * SEQ * DH];
__device__ __half g_X[(size_t)NBL * SEQ * EMB];    // x, fp16
__device__ __half g_WT[(size_t)NCOLS * EMB];       // w^T, fp16

// ============================================================================
// Helpers
// ============================================================================
__device__ __forceinline__ uint32_t smem_u32(const void* p) {
    uint32_t a;
    asm("{ .reg .u64 t; cvta.to.shared.u64 t, %1; cvt.u32.u64 %0, t; }" : "=r"(a) : "l"(p));
    return a;
}

__device__ __forceinline__ void ldsm4(unsigned& r0, unsigned& r1, unsigned& r2,
                                      unsigned& r3, uint32_t addr) {
    asm volatile("ldmatrix.sync.aligned.m8n8.x4.shared.b16 {%0,%1,%2,%3}, [%4];"
                 : "=r"(r0), "=r"(r1), "=r"(r2), "=r"(r3) : "r"(addr));
}
__device__ __forceinline__ void ldsm4t(unsigned& r0, unsigned& r1, unsigned& r2,
                                       unsigned& r3, uint32_t addr) {
    asm volatile("ldmatrix.sync.aligned.m8n8.x4.trans.shared.b16 {%0,%1,%2,%3}, [%4];"
                 : "=r"(r0), "=r"(r1), "=r"(r2), "=r"(r3) : "r"(addr));
}

// D(16x8) += A(16x16) * B(16x8), fp16 in, fp16 accum (2 regs = 4 halves)
__device__ __forceinline__ void mma_f16acc(unsigned* c, const unsigned* a,
                                           const unsigned* b) {
    asm volatile(
        "mma.sync.aligned.m16n8k16.row.col.f16.f16.f16.f16 "
        "{%0,%1}, {%2,%3,%4,%5}, {%6,%7}, {%0,%1};"
        : "+r"(c[0]), "+r"(c[1])
        : "r"(a[0]), "r"(a[1]), "r"(a[2]), "r"(a[3]), "r"(b[0]), "r"(b[1]));
}

__device__ __forceinline__ unsigned packh2(float a, float b) {
    __half2 h = __floats2half2_rn(a, b);
    return *(unsigned*)&h;
}
__device__ __forceinline__ float2 unpkh2(unsigned u) {
    return __half22float2(*reinterpret_cast<__half2*>(&u));
}

#define CP_ASYNC16(dst, src) \
    asm volatile("cp.async.cg.shared.global [%0], [%1], 16;" :: "r"(dst), "l"(src))
#define CP_COMMIT() asm volatile("cp.async.commit_group;" ::: "memory")
#define CP_WAIT2()  asm volatile("cp.async.wait_group 2;" ::: "memory")
#define CP_WAIT1()  asm volatile("cp.async.wait_group 1;" ::: "memory")
#define CP_WAIT0()  asm volatile("cp.async.wait_group 0;" ::: "memory")

// ============================================================================
// Pre-pass: x -> fp16 (g_X); w -> transposed fp16 (g_WT)
// ============================================================================
__global__ __launch_bounds__(256) void cvt_x_kernel(const float* __restrict__ x) {
    const int i = blockIdx.x * 256 + threadIdx.x;        // float4 index
    float4 v = ((const float4*)x)[i];
    uint2 o;
    o.x = packh2(v.x, v.y);
    o.y = packh2(v.z, v.w);
    ((uint2*)g_X)[i] = o;
}

__global__ __launch_bounds__(256) void cvt_wT_kernel(const float* __restrict__ w) {
    __shared__ float tile[32][33];
    const int tx = threadIdx.x & 31;
    const int ty = threadIdx.x >> 5;                     // 0..7
    const int n0 = blockIdx.x * 32;
    const int k0 = blockIdx.y * 32;
#pragma unroll
    for (int r = ty; r < 32; r += 8)
        tile[r][tx] = w[(size_t)(k0 + r) * NCOLS + n0 + tx];
    __syncthreads();
#pragma unroll
    for (int r = ty; r < 32; r += 8)
        g_WT[(size_t)(n0 + r) * EMB + k0 + tx] = __float2half_rn(tile[tx][r]);
}

// ============================================================================
// QKV GEMM: M=8192, N=3072, K=1024, fp16 m16n8k16 + ldmatrix.
// CTA tile 128x64, BK=64 (16 chunks), 2-stage cp.async, one barrier/chunk.
// 4 warps, warp tile 64x32. f16 MMA accumulation WITHIN a chunk (4-chain),
// unpacked into f32 master accumulators across chunks.
// ============================================================================
#define ESTR 72                          // 64 + 8 halves pad -> conflict-free LDSM
#define QKV_A_BYTES (128 * ESTR * 2)     // 18432
#define QKV_B_BYTES (64 * ESTR * 2)      // 9216
#define QKV_STAGE   (QKV_A_BYTES + QKV_B_BYTES)  // 27648
#define QKV_SMEM    (2 * QKV_STAGE)      // 55296 bytes

__global__ __launch_bounds__(128, 3) void qkv_kernel(const float* __restrict__ bias)
{
    extern __shared__ __half qsm[];
    const uint32_t sBase = smem_u32(qsm);

    const int tid  = threadIdx.x;
    const int lane = tid & 31;
    const int warp = tid >> 5;        // 0..3
    const int wm = warp & 1;          // 2 warps along M (64 rows each)
    const int wn = warp >> 1;         // 2 warps along N (32 cols each)
    const int r4 = lane >> 2;
    const int c4 = lane & 3;
    const int lrow = lane & 15;
    const int lch  = (lane >> 4) * 8;

    const int m0 = blockIdx.y * 128;
    const int c0 = blockIdx.x * 64;

    float acc[4][4][4];
#pragma unroll
    for (int i = 0; i < 4; i++)
#pragma unroll
        for (int j = 0; j < 4; j++)
#pragma unroll
            for (int k = 0; k < 4; k++) acc[i][j][k] = 0.f;

    // per stage: A 1024 chunks (8/thread), B 512 chunks (4/thread)
#define QKV_LOAD(kc, s) do { \
    const size_t gk = (size_t)(kc) * 64; \
    const uint32_t aB_ = sBase + (uint32_t)(s) * QKV_STAGE; \
    const uint32_t bB_ = aB_ + QKV_A_BYTES; \
    _Pragma("unroll") \
    for (int i = 0; i < 8; i++) { \
        const int fid = i * 128 + tid; \
        const int row = fid >> 3; \
        const int chh = (fid & 7) * 8; \
        CP_ASYNC16(aB_ + (row * ESTR + chh) * 2, \
                   g_X + (size_t)(m0 + row) * EMB + gk + chh); \
    } \
    _Pragma("unroll") \
    for (int i = 0; i < 4; i++) { \
        const int fid = i * 128 + tid; \
        const int row = fid >> 3; \
        const int chh = (fid & 7) * 8; \
        CP_ASYNC16(bB_ + (row * ESTR + chh) * 2, \
                   g_WT + (size_t)(c0 + row) * EMB + gk + chh); \
    } \
    CP_COMMIT(); \
} while (0)

    QKV_LOAD(0, 0);

#pragma unroll 1
    for (int kc = 0; kc < 16; kc++) {
        CP_WAIT0();                       // stage kc landed (only group pending)
        __syncthreads();                  // all warps done computing stage kc-1
        if (kc + 1 < 16) QKV_LOAD(kc + 1, (kc + 1) & 1);

        const uint32_t aB = sBase + (kc & 1) * QKV_STAGE;
        const uint32_t bB = aB + QKV_A_BYTES;

        // fp16 chunk accumulators (zeroed each chunk)
        unsigned hacc[4][4][2];
#pragma unroll
        for (int mt = 0; mt < 4; mt++)
#pragma unroll
            for (int nt = 0; nt < 4; nt++) {
                hacc[mt][nt][0] = 0u; hacc[mt][nt][1] = 0u;
            }

#pragma unroll
        for (int ks = 0; ks < 4; ks++) {
            unsigned a[4][4];
#pragma unroll
            for (int mt = 0; mt < 4; mt++)
                ldsm4(a[mt][0], a[mt][1], a[mt][2], a[mt][3],
                      aB + ((wm * 64 + mt * 16 + lrow) * ESTR + ks * 16 + lch) * 2);
            unsigned b[4][2];
#pragma unroll
            for (int ntp = 0; ntp < 2; ntp++) {
                unsigned t0, t1, t2, t3;
                ldsm4(t0, t1, t2, t3,
                      bB + ((wn * 32 + ntp * 16 + lrow) * ESTR + ks * 16 + lch) * 2);
                b[2 * ntp][0] = t0; b[2 * ntp][1] = t2;
                b[2 * ntp + 1][0] = t1; b[2 * ntp + 1][1] = t3;
            }
#pragma unroll
            for (int mt = 0; mt < 4; mt++)
#pragma unroll
                for (int nt = 0; nt < 4; nt++)
                    mma_f16acc(hacc[mt][nt], a[mt], b[nt]);
        }

        // unpack chunk partials into f32 master
#pragma unroll
        for (int mt = 0; mt < 4; mt++)
#pragma unroll
            for (int nt = 0; nt < 4; nt++) {
                const float2 f0 = unpkh2(hacc[mt][nt][0]);
                const float2 f1 = unpkh2(hacc[mt][nt][1]);
                acc[mt][nt][0] += f0.x;
                acc[mt][nt][1] += f0.y;
                acc[mt][nt][2] += f1.x;
                acc[mt][nt][3] += f1.y;
            }
    }

    // Epilogue: bias add, fp16, scatter to head-major Q/K/V
#pragma unroll
    for (int mt = 0; mt < 4; mt++) {
        const int mg = m0 + wm * 64 + mt * 16 + r4;
        const int bl = mg >> 9;
        const int n  = mg & 511;
#pragma unroll
        for (int nt = 0; nt < 4; nt++) {
            const int colg = c0 + wn * 32 + nt * 8 + 2 * c4;
            const int which = colg >> 10;
            const int h     = (colg >> 6) & 15;
            const int d     = colg & 63;
            __half* dst = ((which == 0) ? g_Q : (which == 1) ? g_K : g_V)
                        + (size_t)(bl * NHEADS + h) * SEQ * DH + d;
            const float b0 = __ldg(&bias[colg]);
            const float b1 = __ldg(&bias[colg + 1]);
            *(__half2*)(dst + (size_t)n * DH) =
                __floats2half2_rn(acc[mt][nt][0] + b0, acc[mt][nt][1] + b1);
            *(__half2*)(dst + (size_t)(n + 8) * DH) =
                __floats2half2_rn(acc[mt][nt][2] + b0, acc[mt][nt][3] + b1);
        }
    }
}

// ============================================================================
// Fused flash attention: CTA = (head, 64 Q rows), 4 warps x 16 rows.
// 3-stage cp.async K/V pipeline, one barrier per KV block.
// S and PV blocks accumulate in f16 (4-MMA chains); softmax and online-O
// stay f32 (rescale folded into the PV unpack-add).
// ============================================================================
#define PSTR 72
#define KSTR 72
#define KV_BYTES (64 * KSTR * 2)                 // 9216 per matrix per stage
#define ATTN_SMEM (64 * PSTR * 2 + 6 * KV_BYTES) // 64512

__global__ __launch_bounds__(128, 3) void attn_kernel(
    const float* __restrict__ mask, float* __restrict__ out)
{
    extern __shared__ __half asm_[];
    const uint32_t pBase  = smem_u32(asm_);
    const uint32_t kvBase = pBase + 64 * PSTR * 2;

    const int tid  = threadIdx.x;
    const int lane = tid & 31;
    const int warp = tid >> 5;         // 0..3
    const int r4 = lane >> 2;
    const int c4 = lane & 3;
    const int lrow = lane & 15;
    const int lch  = (lane >> 4) * 8;

    const int g  = blockIdx.y;         // bl*16 + h
    const int bl = g >> 4;
    const int h  = g & 15;
    const int q0 = blockIdx.x * 64;
    const int qr0 = warp * 16;

    const __half* Qg = g_Q + (size_t)g * SEQ * DH;
    const __half* Kg = g_K + (size_t)g * SEQ * DH;
    const __half* Vg = g_V + (size_t)g * SEQ * DH;
    const float*  Mg = mask + (size_t)bl * SEQ * SEQ + (size_t)q0 * SEQ;

    // ---- Q staging (cp.async, own commit group) ----
#pragma unroll
    for (int i = 0; i < 4; i++) {
        const int fid = i * 128 + tid;          // 512 chunks
        const int row = fid >> 3;
        const int chh = (fid & 7) * 8;
        CP_ASYNC16(pBase + (row * PSTR + chh) * 2,
                   Qg + (size_t)(q0 + row) * DH + chh);
    }
    CP_COMMIT();

#define KV_LOAD(kb, s) do { \
    const uint32_t kA = kvBase + (uint32_t)(s) * 2 * KV_BYTES; \
    const uint32_t vA = kA + KV_BYTES; \
    const int kk0 = (kb) * 64; \
    _Pragma("unroll") \
    for (int i = 0; i < 4; i++) { \
        const int fid = i * 128 + tid; \
        const int row = fid >> 3; \
        const int chh = (fid & 7) * 8; \
        CP_ASYNC16(kA + (row * KSTR + chh) * 2, Kg + (size_t)(kk0 + row) * DH + chh); \
        CP_ASYNC16(vA + (row * KSTR + chh) * 2, Vg + (size_t)(kk0 + row) * DH + chh); \
    } \
    CP_COMMIT(); \
} while (0)

    KV_LOAD(0, 0);
    KV_LOAD(1, 1);

    CP_WAIT2();                        // Q group done
    __syncthreads();

    unsigned qf[4][4];
#pragma unroll
    for (int kt = 0; kt < 4; kt++)
        ldsm4(qf[kt][0], qf[kt][1], qf[kt][2], qf[kt][3],
              pBase + ((qr0 + lrow) * PSTR + kt * 16 + lch) * 2);

    float m_i0 = -1e30f, m_i1 = -1e30f;
    float l_i0 = 0.f,    l_i1 = 0.f;
    float o[8][4];
#pragma unroll
    for (int nt = 0; nt < 8; nt++)
#pragma unroll
        for (int j = 0; j < 4; j++) o[nt][j] = 0.f;

#pragma unroll 1
    for (int kb = 0; kb < 8; kb++) {
        if (kb < 7) CP_WAIT1(); else CP_WAIT0();
        __syncthreads();               // everyone done with stage (kb+2)%3
        if (kb + 2 < 8) KV_LOAD(kb + 2, (kb + 2) % 3);

        const uint32_t kB = kvBase + (kb % 3) * 2 * KV_BYTES;
        const uint32_t vB = kB + KV_BYTES;
        const int k0 = kb * 64;

        // ---- S = Q K^T  (16x64 per warp), f16 accumulation ----
        unsigned sh[8][2];
#pragma unroll
        for (int nt = 0; nt < 8; nt++) { sh[nt][0] = 0u; sh[nt][1] = 0u; }

#pragma unroll
        for (int kt = 0; kt < 4; kt++) {
#pragma unroll
            for (int ntp = 0; ntp < 4; ntp++) {
                unsigned t0, t1, t2, t3;
                ldsm4(t0, t1, t2, t3,
                      kB + ((ntp * 16 + lrow) * KSTR + kt * 16 + lch) * 2);
                unsigned b0[2] = {t0, t2};
                unsigned b1[2] = {t1, t3};
                mma_f16acc(sh[2 * ntp],     qf[kt], b0);
                mma_f16acc(sh[2 * ntp + 1], qf[kt], b1);
            }
        }

        // ---- unpack to f32, scale + mask, row max ----
        float s[8][4];
        float mx0 = -1e30f, mx1 = -1e30f;
#pragma unroll
        for (int nt = 0; nt < 8; nt++) {
            const float2 f0 = unpkh2(sh[nt][0]);
            const float2 f1 = unpkh2(sh[nt][1]);
            const int col = k0 + nt * 8 + c4 * 2;
            const float* mrow = Mg + (size_t)(qr0 + r4) * SEQ + col;
            const float2 mk0 = *(const float2*)mrow;
            const float2 mk1 = *(const float2*)(mrow + 8 * SEQ);
            s[nt][0] = f0.x * 0.125f + mk0.x;
            s[nt][1] = f0.y * 0.125f + mk0.y;
            s[nt][2] = f1.x * 0.125f + mk1.x;
            s[nt][3] = f1.y * 0.125f + mk1.y;
            mx0 = fmaxf(mx0, fmaxf(s[nt][0], s[nt][1]));
            mx1 = fmaxf(mx1, fmaxf(s[nt][2], s[nt][3]));
        }
        mx0 = fmaxf(mx0, __shfl_xor_sync(0xFFFFFFFFu, mx0, 1));
        mx0 = fmaxf(mx0, __shfl_xor_sync(0xFFFFFFFFu, mx0, 2));
        mx1 = fmaxf(mx1, __shfl_xor_sync(0xFFFFFFFFu, mx1, 1));
        mx1 = fmaxf(mx1, __shfl_xor_sync(0xFFFFFFFFu, mx1, 2));

        const float mn0 = fmaxf(m_i0, mx0);
        const float mn1 = fmaxf(m_i1, mx1);
        const float sc0 = __expf(m_i0 - mn0);
        const float sc1 = __expf(m_i1 - mn1);
        m_i0 = mn0; m_i1 = mn1;

        float sum0 = 0.f, sum1 = 0.f;
#pragma unroll
        for (int nt = 0; nt < 8; nt++) {
            s[nt][0] = __expf(s[nt][0] - mn0);
            s[nt][1] = __expf(s[nt][1] - mn0);
            s[nt][2] = __expf(s[nt][2] - mn1);
            s[nt][3] = __expf(s[nt][3] - mn1);
            sum0 += s[nt][0] + s[nt][1];
            sum1 += s[nt][2] + s[nt][3];
        }
        sum0 += __shfl_xor_sync(0xFFFFFFFFu, sum0, 1);
        sum0 += __shfl_xor_sync(0xFFFFFFFFu, sum0, 2);
        sum1 += __shfl_xor_sync(0xFFFFFFFFu, sum1, 1);
        sum1 += __shfl_xor_sync(0xFFFFFFFFu, sum1, 2);
        l_i0 = l_i0 * sc0 + sum0;
        l_i1 = l_i1 * sc1 + sum1;

        // ---- PV in f16 accumulation, P fragments straight from S ----
        unsigned oh[8][2];
#pragma unroll
        for (int nt = 0; nt < 8; nt++) { oh[nt][0] = 0u; oh[nt][1] = 0u; }

#pragma unroll
        for (int kt = 0; kt < 4; kt++) {
            unsigned pf[4];
            pf[0] = packh2(s[2 * kt][0],     s[2 * kt][1]);
            pf[1] = packh2(s[2 * kt][2],     s[2 * kt][3]);
            pf[2] = packh2(s[2 * kt + 1][0], s[2 * kt + 1][1]);
            pf[3] = packh2(s[2 * kt + 1][2], s[2 * kt + 1][3]);
#pragma unroll
            for (int dtp = 0; dtp < 4; dtp++) {
                unsigned t0, t1, t2, t3;
                ldsm4t(t0, t1, t2, t3,
                       vB + ((kt * 16 + lrow) * KSTR + dtp * 16 + lch) * 2);
                unsigned b0[2] = {t0, t1};
                unsigned b1[2] = {t2, t3};
                mma_f16acc(oh[2 * dtp],     pf, b0);
                mma_f16acc(oh[2 * dtp + 1], pf, b1);
            }
        }

        // ---- fold block PV into online O (rescale fused) ----
#pragma unroll
        for (int nt = 0; nt < 8; nt++) {
            const float2 f0 = unpkh2(oh[nt][0]);
            const float2 f1 = unpkh2(oh[nt][1]);
            o[nt][0] = o[nt][0] * sc0 + f0.x;
            o[nt][1] = o[nt][1] * sc0 + f0.y;
            o[nt][2] = o[nt][2] * sc1 + f1.x;
            o[nt][3] = o[nt][3] * sc1 + f1.y;
        }
    }

    // ---- normalize + write out ----
    const float inv0 = 1.f / l_i0;
    const float inv1 = 1.f / l_i1;
    const int grow = q0 + qr0 + r4;
    float* outp = out + (size_t)(bl * SEQ + grow) * EMB + h * DH;
#pragma unroll
    for (int nt = 0; nt < 8; nt++) {
        const int col = nt * 8 + c4 * 2;
        *(float2*)(outp + col) =
            make_float2(o[nt][0] * inv0, o[nt][1] * inv0);
        *(float2*)(outp + (size_t)8 * EMB + col) =
            make_float2(o[nt][2] * inv1, o[nt][3] * inv1);
    }
}

// ============================================================================
// Launch (serial R9 structure — stream overlap reverted)
// ============================================================================
extern "C" void kernel_launch(void* const* d_in, const int* in_sizes, int n_in,
                              void* d_out, int out_size)
{
    const float* x = nullptr; const float* mask = nullptr;
    const float* w = nullptr; const float* bias = nullptr;
    for (int i = 0; i < n_in; i++) {
        switch (in_sizes[i]) {
            case 8388608: x    = (const float*)d_in[i]; break;  // 4*4*512*1024
            case 4194304: mask = (const float*)d_in[i]; break;  // 4*4*512*512
            case 3145728: w    = (const float*)d_in[i]; break;  // 1024*3072
            case 3072:    bias = (const float*)d_in[i]; break;
        }
    }
    float* out = (float*)d_out;

    cvt_x_kernel<<<8192, 256>>>(x);
    cvt_wT_kernel<<<dim3(96, 32), 256>>>(w);

    cudaFuncSetAttribute(qkv_kernel,
                         cudaFuncAttributeMaxDynamicSharedMemorySize, QKV_SMEM);
    dim3 gQ(48, 64);                                // 3072/64 x 8192/128
    qkv_kernel<<<gQ, 128, QKV_SMEM>>>(bias);

    cudaFuncSetAttribute(attn_kernel,
                         cudaFuncAttributeMaxDynamicSharedMemorySize, ATTN_SMEM);
    dim3 gB(8, 256);                                // 8 q-blocks x 256 heads
    attn_kernel<<<gB, 128, ATTN_SMEM>>>(mask, out);
}

// round 13
// speedup vs baseline: 1.0386x; 1.0383x over previous
#include <cuda_runtime.h>
#include <cuda_fp16.h>
#include <cstdint>

// Problem constants (fixed by setup_inputs)
#define NBL    16      // b*l
#define NHEADS 16
#define SEQ    512
#define DH     64
#define EMB    1024
#define NCOLS  3072    // 3*EMB

// fp16 scratch: head-major Q/K/V [bl][h][n][d]; converted inputs
__device__ __half g_Q[(size_t)NBL * NHEADS * SEQ * DH];
__device__ __half g_K[(size_t)NBL * NHEADS * SEQ * DH];
__device__ __half g_V[(size_t)NBL * NHEADS * SEQ * DH];
__device__ __half g_X[(size_t)NBL * SEQ * EMB];    // x, fp16
__device__ __half g_WT[(size_t)NCOLS * EMB];       // w^T, fp16

// Work-queue state (reset by zero_kernel each launch/replay)
__device__ int g_next;
__device__ int g_qkv_done[NBL];     // target 192 each

#define N_QKV    3072
#define N_ATTN   2048
#define TOTAL_ITEMS (N_QKV + N_ATTN)   // 5120
#define QKV_PER_BL 192

// ============================================================================
// Helpers
// ============================================================================
__device__ __forceinline__ uint32_t smem_u32(const void* p) {
    uint32_t a;
    asm("{ .reg .u64 t; cvta.to.shared.u64 t, %1; cvt.u32.u64 %0, t; }" : "=r"(a) : "l"(p));
    return a;
}
__device__ __forceinline__ void ldsm4(unsigned& r0, unsigned& r1, unsigned& r2,
                                      unsigned& r3, uint32_t addr) {
    asm volatile("ldmatrix.sync.aligned.m8n8.x4.shared.b16 {%0,%1,%2,%3}, [%4];"
                 : "=r"(r0), "=r"(r1), "=r"(r2), "=r"(r3) : "r"(addr));
}
__device__ __forceinline__ void ldsm4t(unsigned& r0, unsigned& r1, unsigned& r2,
                                       unsigned& r3, uint32_t addr) {
    asm volatile("ldmatrix.sync.aligned.m8n8.x4.trans.shared.b16 {%0,%1,%2,%3}, [%4];"
                 : "=r"(r0), "=r"(r1), "=r"(r2), "=r"(r3) : "r"(addr));
}
__device__ __forceinline__ void mma_f16(float* c, const unsigned* a, const unsigned* b) {
    asm volatile(
        "mma.sync.aligned.m16n8k16.row.col.f32.f16.f16.f32 "
        "{%0,%1,%2,%3}, {%4,%5,%6,%7}, {%8,%9}, {%0,%1,%2,%3};"
        : "+f"(c[0]), "+f"(c[1]), "+f"(c[2]), "+f"(c[3])
        : "r"(a[0]), "r"(a[1]), "r"(a[2]), "r"(a[3]), "r"(b[0]), "r"(b[1]));
}
__device__ __forceinline__ unsigned packh2(float a, float b) {
    __half2 h = __floats2half2_rn(a, b);
    return *(unsigned*)&h;
}
__device__ __forceinline__ int ld_acq(const int* p) {
    int v;
    asm volatile("ld.global.acquire.gpu.b32 %0, [%1];" : "=r"(v) : "l"(p));
    return v;
}

#define CP_ASYNC16(dst, src) \
    asm volatile("cp.async.cg.shared.global [%0], [%1], 16;" :: "r"(dst), "l"(src))
#define CP_COMMIT() asm volatile("cp.async.commit_group;" ::: "memory")
#define CP_WAIT2()  asm volatile("cp.async.wait_group 2;" ::: "memory")
#define CP_WAIT1()  asm volatile("cp.async.wait_group 1;" ::: "memory")
#define CP_WAIT0()  asm volatile("cp.async.wait_group 0;" ::: "memory")

// ============================================================================
// Pre-pass kernels (separate launches — proven R9 form)
// ============================================================================
__global__ __launch_bounds__(256) void cvt_x_kernel(const float* __restrict__ x) {
    const int i = blockIdx.x * 256 + threadIdx.x;        // float4 index
    float4 v = ((const float4*)x)[i];
    uint2 o;
    o.x = packh2(v.x, v.y);
    o.y = packh2(v.z, v.w);
    ((uint2*)g_X)[i] = o;
}

__global__ __launch_bounds__(256) void cvt_wT_kernel(const float* __restrict__ w) {
    __shared__ float tile[32][33];
    const int tx = threadIdx.x & 31;
    const int ty = threadIdx.x >> 5;                     // 0..7
    const int n0 = blockIdx.x * 32;
    const int k0 = blockIdx.y * 32;
#pragma unroll
    for (int r = ty; r < 32; r += 8)
        tile[r][tx] = w[(size_t)(k0 + r) * NCOLS + n0 + tx];
    __syncthreads();
#pragma unroll
    for (int r = ty; r < 32; r += 8)
        g_WT[(size_t)(n0 + r) * EMB + k0 + tx] = __float2half_rn(tile[tx][r]);
}

// ============================================================================
// Item bodies (128 threads; dsm = dynamic smem base). Bit-identical math to R9.
// ============================================================================
#define ESTR 72
#define QKV_A_BYTES (128 * ESTR * 2)     // 18432
#define QKV_B_BYTES (64 * ESTR * 2)      // 9216
#define QKV_STAGE   (QKV_A_BYTES + QKV_B_BYTES)  // 27648

__device__ void do_qkv(const float* __restrict__ bias, char* dsm, int item, int tid) {
    const uint32_t sBase = smem_u32(dsm);
    const int lane = tid & 31;
    const int warp = tid >> 5;        // 0..3
    const int wm = warp & 1;
    const int wn = warp >> 1;
    const int r4 = lane >> 2;
    const int c4 = lane & 3;
    const int lrow = lane & 15;
    const int lch  = (lane >> 4) * 8;

    const int m0 = (item / 48) * 128;
    const int c0 = (item % 48) * 64;

    float acc[4][4][4];
#pragma unroll
    for (int i = 0; i < 4; i++)
#pragma unroll
        for (int j = 0; j < 4; j++)
#pragma unroll
            for (int k = 0; k < 4; k++) acc[i][j][k] = 0.f;

#define QKV_LOAD(kc, s) do { \
    const size_t gk = (size_t)(kc) * 64; \
    const uint32_t aB_ = sBase + (uint32_t)(s) * QKV_STAGE; \
    const uint32_t bB_ = aB_ + QKV_A_BYTES; \
    _Pragma("unroll") \
    for (int i = 0; i < 8; i++) { \
        const int fid = i * 128 + tid; \
        const int row = fid >> 3; \
        const int chh = (fid & 7) * 8; \
        CP_ASYNC16(aB_ + (row * ESTR + chh) * 2, \
                   g_X + (size_t)(m0 + row) * EMB + gk + chh); \
    } \
    _Pragma("unroll") \
    for (int i = 0; i < 4; i++) { \
        const int fid = i * 128 + tid; \
        const int row = fid >> 3; \
        const int chh = (fid & 7) * 8; \
        CP_ASYNC16(bB_ + (row * ESTR + chh) * 2, \
                   g_WT + (size_t)(c0 + row) * EMB + gk + chh); \
    } \
    CP_COMMIT(); \
} while (0)

    QKV_LOAD(0, 0);

#pragma unroll 1
    for (int kc = 0; kc < 16; kc++) {
        CP_WAIT0();
        __syncthreads();
        if (kc + 1 < 16) QKV_LOAD(kc + 1, (kc + 1) & 1);

        const uint32_t aB = sBase + (kc & 1) * QKV_STAGE;
        const uint32_t bB = aB + QKV_A_BYTES;

#pragma unroll
        for (int ks = 0; ks < 4; ks++) {
            unsigned a[4][4];
#pragma unroll
            for (int mt = 0; mt < 4; mt++)
                ldsm4(a[mt][0], a[mt][1], a[mt][2], a[mt][3],
                      aB + ((wm * 64 + mt * 16 + lrow) * ESTR + ks * 16 + lch) * 2);
            unsigned b[4][2];
#pragma unroll
            for (int ntp = 0; ntp < 2; ntp++) {
                unsigned t0, t1, t2, t3;
                ldsm4(t0, t1, t2, t3,
                      bB + ((wn * 32 + ntp * 16 + lrow) * ESTR + ks * 16 + lch) * 2);
                b[2 * ntp][0] = t0; b[2 * ntp][1] = t2;
                b[2 * ntp + 1][0] = t1; b[2 * ntp + 1][1] = t3;
            }
#pragma unroll
            for (int mt = 0; mt < 4; mt++)
#pragma unroll
                for (int nt = 0; nt < 4; nt++)
                    mma_f16(acc[mt][nt], a[mt], b[nt]);
        }
    }

#pragma unroll
    for (int mt = 0; mt < 4; mt++) {
        const int mg = m0 + wm * 64 + mt * 16 + r4;
        const int bl = mg >> 9;
        const int n  = mg & 511;
#pragma unroll
        for (int nt = 0; nt < 4; nt++) {
            const int colg = c0 + wn * 32 + nt * 8 + 2 * c4;
            const int which = colg >> 10;
            const int h     = (colg >> 6) & 15;
            const int d     = colg & 63;
            __half* dst = ((which == 0) ? g_Q : (which == 1) ? g_K : g_V)
                        + (size_t)(bl * NHEADS + h) * SEQ * DH + d;
            const float b0 = __ldg(&bias[colg]);
            const float b1 = __ldg(&bias[colg + 1]);
            *(__half2*)(dst + (size_t)n * DH) =
                __floats2half2_rn(acc[mt][nt][0] + b0, acc[mt][nt][1] + b1);
            *(__half2*)(dst + (size_t)(n + 8) * DH) =
                __floats2half2_rn(acc[mt][nt][2] + b0, acc[mt][nt][3] + b1);
        }
    }
}

#define PSTR 72
#define KSTR 72
#define KV_BYTES (64 * KSTR * 2)                 // 9216
#define ATTN_SMEM (64 * PSTR * 2 + 6 * KV_BYTES) // 64512
#define DYN_SMEM  ATTN_SMEM

__device__ void do_attn(const float* __restrict__ mask, float* __restrict__ out,
                        char* dsm, int item, int tid) {
    const uint32_t pBase  = smem_u32(dsm);
    const uint32_t kvBase = pBase + 64 * PSTR * 2;

    const int lane = tid & 31;
    const int warp = tid >> 5;
    const int r4 = lane >> 2;
    const int c4 = lane & 3;
    const int lrow = lane & 15;
    const int lch  = (lane >> 4) * 8;

    const int g  = item >> 3;          // bl*16 + h
    const int bl = g >> 4;
    const int h  = g & 15;
    const int q0 = (item & 7) * 64;
    const int qr0 = warp * 16;

    const __half* Qg = g_Q + (size_t)g * SEQ * DH;
    const __half* Kg = g_K + (size_t)g * SEQ * DH;
    const __half* Vg = g_V + (size_t)g * SEQ * DH;
    const float*  Mg = mask + (size_t)bl * SEQ * SEQ + (size_t)q0 * SEQ;

#pragma unroll
    for (int i = 0; i < 4; i++) {
        const int fid = i * 128 + tid;
        const int row = fid >> 3;
        const int chh = (fid & 7) * 8;
        CP_ASYNC16(pBase + (row * PSTR + chh) * 2,
                   Qg + (size_t)(q0 + row) * DH + chh);
    }
    CP_COMMIT();

#define KV_LOAD(kb, s) do { \
    const uint32_t kA = kvBase + (uint32_t)(s) * 2 * KV_BYTES; \
    const uint32_t vA = kA + KV_BYTES; \
    const int kk0 = (kb) * 64; \
    _Pragma("unroll") \
    for (int i = 0; i < 4; i++) { \
        const int fid = i * 128 + tid; \
        const int row = fid >> 3; \
        const int chh = (fid & 7) * 8; \
        CP_ASYNC16(kA + (row * KSTR + chh) * 2, Kg + (size_t)(kk0 + row) * DH + chh); \
        CP_ASYNC16(vA + (row * KSTR + chh) * 2, Vg + (size_t)(kk0 + row) * DH + chh); \
    } \
    CP_COMMIT(); \
} while (0)

    KV_LOAD(0, 0);
    KV_LOAD(1, 1);

    CP_WAIT2();
    __syncthreads();

    unsigned qf[4][4];
#pragma unroll
    for (int kt = 0; kt < 4; kt++)
        ldsm4(qf[kt][0], qf[kt][1], qf[kt][2], qf[kt][3],
              pBase + ((qr0 + lrow) * PSTR + kt * 16 + lch) * 2);

    float m_i0 = -1e30f, m_i1 = -1e30f;
    float l_i0 = 0.f,    l_i1 = 0.f;
    float o[8][4];
#pragma unroll
    for (int nt = 0; nt < 8; nt++)
#pragma unroll
        for (int j = 0; j < 4; j++) o[nt][j] = 0.f;

#pragma unroll 1
    for (int kb = 0; kb < 8; kb++) {
        if (kb < 7) CP_WAIT1(); else CP_WAIT0();
        __syncthreads();
        if (kb + 2 < 8) KV_LOAD(kb + 2, (kb + 2) % 3);

        const uint32_t kB = kvBase + (kb % 3) * 2 * KV_BYTES;
        const uint32_t vB = kB + KV_BYTES;
        const int k0 = kb * 64;

        float s[8][4];
#pragma unroll
        for (int nt = 0; nt < 8; nt++)
#pragma unroll
            for (int j = 0; j < 4; j++) s[nt][j] = 0.f;

#pragma unroll
        for (int kt = 0; kt < 4; kt++) {
#pragma unroll
            for (int ntp = 0; ntp < 4; ntp++) {
                unsigned t0, t1, t2, t3;
                ldsm4(t0, t1, t2, t3,
                      kB + ((ntp * 16 + lrow) * KSTR + kt * 16 + lch) * 2);
                unsigned b0[2] = {t0, t2};
                unsigned b1[2] = {t1, t3};
                mma_f16(s[2 * ntp],     qf[kt], b0);
                mma_f16(s[2 * ntp + 1], qf[kt], b1);
            }
        }

        float mx0 = -1e30f, mx1 = -1e30f;
#pragma unroll
        for (int nt = 0; nt < 8; nt++) {
            const int col = k0 + nt * 8 + c4 * 2;
            const float* mrow = Mg + (size_t)(qr0 + r4) * SEQ + col;
            const float2 mk0 = *(const float2*)mrow;
            const float2 mk1 = *(const float2*)(mrow + 8 * SEQ);
            s[nt][0] = s[nt][0] * 0.125f + mk0.x;
            s[nt][1] = s[nt][1] * 0.125f + mk0.y;
            s[nt][2] = s[nt][2] * 0.125f + mk1.x;
            s[nt][3] = s[nt][3] * 0.125f + mk1.y;
            mx0 = fmaxf(mx0, fmaxf(s[nt][0], s[nt][1]));
            mx1 = fmaxf(mx1, fmaxf(s[nt][2], s[nt][3]));
        }
        mx0 = fmaxf(mx0, __shfl_xor_sync(0xFFFFFFFFu, mx0, 1));
        mx0 = fmaxf(mx0, __shfl_xor_sync(0xFFFFFFFFu, mx0, 2));
        mx1 = fmaxf(mx1, __shfl_xor_sync(0xFFFFFFFFu, mx1, 1));
        mx1 = fmaxf(mx1, __shfl_xor_sync(0xFFFFFFFFu, mx1, 2));

        const float mn0 = fmaxf(m_i0, mx0);
        const float mn1 = fmaxf(m_i1, mx1);
        const float sc0 = __expf(m_i0 - mn0);
        const float sc1 = __expf(m_i1 - mn1);
        m_i0 = mn0; m_i1 = mn1;

        float sum0 = 0.f, sum1 = 0.f;
#pragma unroll
        for (int nt = 0; nt < 8; nt++) {
            s[nt][0] = __expf(s[nt][0] - mn0);
            s[nt][1] = __expf(s[nt][1] - mn0);
            s[nt][2] = __expf(s[nt][2] - mn1);
            s[nt][3] = __expf(s[nt][3] - mn1);
            sum0 += s[nt][0] + s[nt][1];
            sum1 += s[nt][2] + s[nt][3];
        }
        sum0 += __shfl_xor_sync(0xFFFFFFFFu, sum0, 1);
        sum0 += __shfl_xor_sync(0xFFFFFFFFu, sum0, 2);
        sum1 += __shfl_xor_sync(0xFFFFFFFFu, sum1, 1);
        sum1 += __shfl_xor_sync(0xFFFFFFFFu, sum1, 2);
        l_i0 = l_i0 * sc0 + sum0;
        l_i1 = l_i1 * sc1 + sum1;

#pragma unroll
        for (int nt = 0; nt < 8; nt++) {
            o[nt][0] *= sc0; o[nt][1] *= sc0;
            o[nt][2] *= sc1; o[nt][3] *= sc1;
        }

#pragma unroll
        for (int kt = 0; kt < 4; kt++) {
            unsigned pf[4];
            pf[0] = packh2(s[2 * kt][0],     s[2 * kt][1]);
            pf[1] = packh2(s[2 * kt][2],     s[2 * kt][3]);
            pf[2] = packh2(s[2 * kt + 1][0], s[2 * kt + 1][1]);
            pf[3] = packh2(s[2 * kt + 1][2], s[2 * kt + 1][3]);
#pragma unroll
            for (int dtp = 0; dtp < 4; dtp++) {
                unsigned t0, t1, t2, t3;
                ldsm4t(t0, t1, t2, t3,
                       vB + ((kt * 16 + lrow) * KSTR + dtp * 16 + lch) * 2);
                unsigned b0[2] = {t0, t1};
                unsigned b1[2] = {t2, t3};
                mma_f16(o[2 * dtp],     pf, b0);
                mma_f16(o[2 * dtp + 1], pf, b1);
            }
        }
    }

    const float inv0 = 1.f / l_i0;
    const float inv1 = 1.f / l_i1;
    const int grow = q0 + qr0 + r4;
    float* outp = out + (size_t)(bl * SEQ + grow) * EMB + h * DH;
#pragma unroll
    for (int nt = 0; nt < 8; nt++) {
        const int col = nt * 8 + c4 * 2;
        *(float2*)(outp + col) =
            make_float2(o[nt][0] * inv0, o[nt][1] * inv0);
        *(float2*)(outp + (size_t)8 * EMB + col) =
            make_float2(o[nt][2] * inv1, o[nt][3] * inv1);
    }
}

// ============================================================================
// Counter reset (same stream, before the persistent kernel, every replay)
// ============================================================================
__global__ void zero_kernel() {
    if (threadIdx.x == 0) g_next = 0;
    if (threadIdx.x < NBL) g_qkv_done[threadIdx.x] = 0;
}

// ============================================================================
// Persistent qkv+attn work-queue kernel
// ============================================================================
__global__ __launch_bounds__(128, 3) void fused_kernel(
    const float* __restrict__ bias, const float* __restrict__ mask,
    float* __restrict__ out)
{
    extern __shared__ char dsm[];
    __shared__ int s_item;
    const int tid = threadIdx.x;

    for (;;) {
        __syncthreads();                       // prev item done with smem
        if (tid == 0) s_item = atomicAdd(&g_next, 1);
        __syncthreads();
        const int it = s_item;
        if (it >= TOTAL_ITEMS) break;

        if (it < N_QKV) {
            do_qkv(bias, dsm, it, tid);
            __threadfence();                   // each thread's stores -> gpu scope
            __syncthreads();                   // all threads fenced
            if (tid == 0) atomicAdd(&g_qkv_done[(it / 48) >> 2], 1);
        } else {
            const int a = it - N_QKV;
            if (tid == 0) {
                while (ld_acq(&g_qkv_done[a >> 7]) < QKV_PER_BL) __nanosleep(100);
            }
            __syncthreads();
            do_attn(mask, out, dsm, a, tid);
        }
    }
}

// ============================================================================
// Launch
// ============================================================================
extern "C" void kernel_launch(void* const* d_in, const int* in_sizes, int n_in,
                              void* d_out, int out_size)
{
    const float* x = nullptr; const float* mask = nullptr;
    const float* w = nullptr; const float* bias = nullptr;
    for (int i = 0; i < n_in; i++) {
        switch (in_sizes[i]) {
            case 8388608: x    = (const float*)d_in[i]; break;  // 4*4*512*1024
            case 4194304: mask = (const float*)d_in[i]; break;  // 4*4*512*512
            case 3145728: w    = (const float*)d_in[i]; break;  // 1024*3072
            case 3072:    bias = (const float*)d_in[i]; break;
        }
    }
    float* out = (float*)d_out;

    zero_kernel<<<1, 32>>>();
    cvt_x_kernel<<<8192, 256>>>(x);
    cvt_wT_kernel<<<dim3(96, 32), 256>>>(w);

    cudaFuncSetAttribute(fused_kernel,
                         cudaFuncAttributeMaxDynamicSharedMemorySize, DYN_SMEM);
    fused_kernel<<<444, 128, DYN_SMEM>>>(bias, mask, out);
}